// round 1
// baseline (speedup 1.0000x reference)
#include <cuda_runtime.h>
#include <cuda_bf16.h>
#include <cstdint>

// Problem constants
#define BB   8
#define CC   256
#define HH   128
#define WW   128
#define GG   8       // ska groups (32 ch each)
#define NPIX 16384   // H*W
#define EPSV 1e-5f

// Scratch (device globals; allocation-free rule)
__device__ float g_ska[BB * CC * NPIX];   // SKA output (residual + conv input)
__device__ float g_t[BB * CC * NPIX];     // after conv3x3+BN+ReLU
__device__ float g_w2t[CC * CC];          // transposed w2 with s2 folded
__device__ float g_s1[CC], g_bb1[CC], g_s2[CC], g_bb2[CC];

// ---------- packed f32x2 helpers ----------
__device__ __forceinline__ unsigned long long pack2(float a, float b) {
    unsigned long long r;
    asm("mov.b64 %0, {%1, %2};" : "=l"(r) : "f"(a), "f"(b));
    return r;
}
__device__ __forceinline__ unsigned long long fma2(unsigned long long a,
                                                   unsigned long long b,
                                                   unsigned long long c) {
    unsigned long long d;
    asm("fma.rn.f32x2 %0, %1, %2, %3;" : "=l"(d) : "l"(a), "l"(b), "l"(c));
    return d;
}
__device__ __forceinline__ float2 unpack2(unsigned long long v) {
    float2 f;
    asm("mov.b64 {%0, %1}, %2;" : "=f"(f.x), "=f"(f.y) : "l"(v));
    return f;
}

// ---------- prep: fold BN params ----------
__global__ void prep_bn(const float* __restrict__ g1, const float* __restrict__ b1,
                        const float* __restrict__ m1, const float* __restrict__ v1,
                        const float* __restrict__ g2, const float* __restrict__ b2,
                        const float* __restrict__ m2, const float* __restrict__ v2) {
    int c = threadIdx.x;
    if (c < CC) {
        float i1 = g1[c] * rsqrtf(v1[c] + EPSV);
        g_s1[c]  = i1;
        g_bb1[c] = b1[c] - m1[c] * i1;
        float i2 = g2[c] * rsqrtf(v2[c] + EPSV);
        g_s2[c]  = i2;
        g_bb2[c] = b2[c] - m2[c] * i2;
    }
}

// ---------- prep: transpose w2 with s2 fold ----------
__global__ void prep_w2t(const float* __restrict__ w2) {
    int i  = blockIdx.x * 256 + threadIdx.x;  // 65536 total
    int co = i >> 8;
    int ci = i & 255;
    g_w2t[ci * 256 + co] = w2[i] * g_s2[co];
}

// ---------- SKA: spatially-varying 3x3 aggregation ----------
// grid (H, B*G), block 128 (one per w). dw shared across the 32 channels of a group.
__global__ void ska_kernel(const float* __restrict__ x, const float* __restrict__ dw) {
    int h  = blockIdx.x;
    int bg = blockIdx.y;                 // b*G + g
    int b  = bg >> 3, g = bg & 7;
    int w  = threadIdx.x;

    __shared__ float rows[3][130];
    if (w < 2) {                         // zero halo columns (never overwritten)
        rows[0][w * 129] = 0.f;
        rows[1][w * 129] = 0.f;
        rows[2][w * 129] = 0.f;
    }

    float dwv[9];
    const float* dp = dw + (size_t)bg * 9 * NPIX + h * WW + w;
#pragma unroll
    for (int k = 0; k < 9; ++k) dwv[k] = dp[k * NPIX];

    const float* xb = x + (size_t)(b * CC + g * 32) * NPIX;
    float* ob = g_ska + (size_t)(b * CC + g * 32) * NPIX + h * WW + w;

    for (int c = 0; c < 32; ++c) {
        __syncthreads();
        const float* xc = xb + c * NPIX;
#pragma unroll
        for (int r = 0; r < 3; ++r) {
            int hh = h + r - 1;
            rows[r][w + 1] = ((unsigned)hh < (unsigned)HH) ? xc[hh * WW + w] : 0.f;
        }
        __syncthreads();
        float acc = 0.f;
#pragma unroll
        for (int r = 0; r < 3; ++r)
#pragma unroll
            for (int kw = 0; kw < 3; ++kw)
                acc = fmaf(rows[r][w + kw], dwv[r * 3 + kw], acc);
        ob[c * NPIX] = acc;
    }
}

// ---------- grouped 3x3 conv + BN + ReLU (f32x2) ----------
// grid (8,8,B*8): 16x16 pixel tile per block, one conv-group (32 in -> 32 out).
// 256 threads: tid>>7 selects cout half (16 couts, as 8 pairs), tid&127 -> 2 pixels.
__global__ void conv3_kernel(const float* __restrict__ roi, const float* __restrict__ w1) {
    int bz  = blockIdx.z;
    int b   = bz >> 3, vg = bz & 7;
    int px0 = blockIdx.x * 16, py0 = blockIdx.y * 16;
    int tid = threadIdx.x;

    __shared__ float ws2[288 * 34];   // [k = cin*9+tap][co padded to 34]
    __shared__ float xt[18][19];

    // stage weights (coalesced read), fold s1, transposed write (pad 34 -> <=2-way STS)
    {
        const float* slab = w1 + vg * 32 * 288;  // w1[(vg*32+co)*288 + k]
        for (int j = tid; j < 9216; j += 256) {
            int co = j / 288;
            int k  = j - co * 288;
            ws2[k * 34 + co] = slab[j] * g_s1[vg * 32 + co];
        }
    }

    int coh = tid >> 7;          // 0/1
    int pt  = tid & 127;
    int py  = pt >> 3;           // 0..15
    int px  = (pt & 7) * 2;      // 0..14 even

    unsigned long long acc[8][2]; // [co pair][pixel], each = {co, co+1}
#pragma unroll
    for (int i = 0; i < 8; ++i) { acc[i][0] = 0ull; acc[i][1] = 0ull; }

    const float* rp = roi + b * NPIX;

    for (int cin = 0; cin < 32; ++cin) {
        __syncthreads();
        const float* sp = g_ska + (size_t)(b * CC + vg * 32 + cin) * NPIX;
        for (int i = tid; i < 324; i += 256) {
            int r  = i / 18, cc2 = i - r * 18;
            int hh = py0 + r - 1, ww2 = px0 + cc2 - 1;
            float v = 0.f;
            if ((unsigned)hh < (unsigned)HH && (unsigned)ww2 < (unsigned)WW) {
                int off = hh * WW + ww2;
                v = sp[off] * rp[off];
            }
            xt[r][cc2] = v;
        }
        __syncthreads();

        float xv[12];
#pragma unroll
        for (int r = 0; r < 3; ++r)
#pragma unroll
            for (int q = 0; q < 4; ++q)
                xv[r * 4 + q] = xt[py + r][px + q];

        const float* wkbase = ws2 + cin * 9 * 34 + coh * 16;
#pragma unroll
        for (int tap = 0; tap < 9; ++tap) {
            int r = tap / 3, kw = tap - r * 3;
            unsigned long long x0 = pack2(xv[r * 4 + kw],     xv[r * 4 + kw]);
            unsigned long long x1 = pack2(xv[r * 4 + kw + 1], xv[r * 4 + kw + 1]);
            const float* wk = wkbase + tap * 34;
#pragma unroll
            for (int c2 = 0; c2 < 8; ++c2) {
                unsigned long long wv = *(const unsigned long long*)(wk + c2 * 2);
                acc[c2][0] = fma2(wv, x0, acc[c2][0]);
                acc[c2][1] = fma2(wv, x1, acc[c2][1]);
            }
        }
    }

    int hy = py0 + py, wx = px0 + px;
#pragma unroll
    for (int c2 = 0; c2 < 8; ++c2) {
        int cg = vg * 32 + coh * 16 + c2 * 2;
        float2 e0 = unpack2(acc[c2][0]);  // pixel wx   : (co, co+1)
        float2 e1 = unpack2(acc[c2][1]);  // pixel wx+1 : (co, co+1)
        float bbA = g_bb1[cg], bbB = g_bb1[cg + 1];
        float2 oA = make_float2(fmaxf(e0.x + bbA, 0.f), fmaxf(e1.x + bbA, 0.f));
        float2 oB = make_float2(fmaxf(e0.y + bbB, 0.f), fmaxf(e1.y + bbB, 0.f));
        size_t oa = (size_t)(b * CC + cg) * NPIX + hy * WW + wx;
        *(float2*)(g_t + oa)        = oA;
        *(float2*)(g_t + oa + NPIX) = oB;
    }
}

// ---------- 1x1 conv (GEMM) + BN + residual (f32x2) ----------
// grid (256, 2, B): p-tile of 64, co-tile of 128. 256 threads: thread = 8 co x 4 p.
__global__ void conv1x1_kernel(float* __restrict__ out) {
    int p0  = blockIdx.x * 64;
    int co0 = blockIdx.y * 128;
    int b   = blockIdx.z;
    int tid = threadIdx.x;
    int tx  = tid & 15;   // p direction (4 p each)
    int ty  = tid >> 4;   // co direction (8 co each)

    __shared__ float As[16][128];  // w2t[k][co]  (s2 folded)
    __shared__ float Bs[16][64];   // t[k][p]

    unsigned long long acc[4][4];  // [co pair][p], each = {co, co+1}
#pragma unroll
    for (int i = 0; i < 4; ++i)
#pragma unroll
        for (int j = 0; j < 4; ++j) acc[i][j] = 0ull;

    const float* tb = g_t + (size_t)b * CC * NPIX;

    for (int kb = 0; kb < 16; ++kb) {
        __syncthreads();
        for (int i = tid; i < 2048; i += 256) {
            int kk = i >> 7, c = i & 127;
            As[kk][c] = g_w2t[(kb * 16 + kk) * 256 + co0 + c];
        }
        for (int i = tid; i < 1024; i += 256) {
            int kk = i >> 6, pp = i & 63;
            Bs[kk][pp] = tb[(size_t)(kb * 16 + kk) * NPIX + p0 + pp];
        }
        __syncthreads();
#pragma unroll
        for (int kk = 0; kk < 16; ++kk) {
            float4 bv = *(const float4*)&Bs[kk][tx * 4];
            unsigned long long bp0 = pack2(bv.x, bv.x);
            unsigned long long bp1 = pack2(bv.y, bv.y);
            unsigned long long bp2 = pack2(bv.z, bv.z);
            unsigned long long bp3 = pack2(bv.w, bv.w);
            const float* ar = &As[kk][ty * 8];
#pragma unroll
            for (int c2 = 0; c2 < 4; ++c2) {
                unsigned long long wv = *(const unsigned long long*)(ar + c2 * 2);
                acc[c2][0] = fma2(wv, bp0, acc[c2][0]);
                acc[c2][1] = fma2(wv, bp1, acc[c2][1]);
                acc[c2][2] = fma2(wv, bp2, acc[c2][2]);
                acc[c2][3] = fma2(wv, bp3, acc[c2][3]);
            }
        }
    }

    // epilogue: out = ska + dot + bb2
#pragma unroll
    for (int c2 = 0; c2 < 4; ++c2) {
        int co = co0 + ty * 8 + c2 * 2;
        float2 f0 = unpack2(acc[c2][0]);
        float2 f1 = unpack2(acc[c2][1]);
        float2 f2 = unpack2(acc[c2][2]);
        float2 f3 = unpack2(acc[c2][3]);
        float bbA = g_bb2[co], bbB = g_bb2[co + 1];
        size_t i0 = (size_t)(b * CC + co) * NPIX + p0 + tx * 4;
        float4 s0 = *(const float4*)(g_ska + i0);
        float4 s1v = *(const float4*)(g_ska + i0 + NPIX);
        float4 o0 = make_float4(s0.x + f0.x + bbA, s0.y + f1.x + bbA,
                                s0.z + f2.x + bbA, s0.w + f3.x + bbA);
        float4 o1 = make_float4(s1v.x + f0.y + bbB, s1v.y + f1.y + bbB,
                                s1v.z + f2.y + bbB, s1v.w + f3.y + bbB);
        *(float4*)(out + i0)        = o0;
        *(float4*)(out + i0 + NPIX) = o1;
    }
}

extern "C" void kernel_launch(void* const* d_in, const int* in_sizes, int n_in,
                              void* d_out, int out_size) {
    const float* x   = (const float*)d_in[0];
    const float* dw  = (const float*)d_in[1];
    const float* roi = (const float*)d_in[2];
    const float* w1  = (const float*)d_in[3];
    const float* g1  = (const float*)d_in[4];
    const float* b1  = (const float*)d_in[5];
    const float* m1  = (const float*)d_in[6];
    const float* v1  = (const float*)d_in[7];
    const float* w2  = (const float*)d_in[8];
    const float* g2  = (const float*)d_in[9];
    const float* b2  = (const float*)d_in[10];
    const float* m2  = (const float*)d_in[11];
    const float* v2  = (const float*)d_in[12];
    float* out = (float*)d_out;

    prep_bn<<<1, 256>>>(g1, b1, m1, v1, g2, b2, m2, v2);
    prep_w2t<<<256, 256>>>(w2);
    ska_kernel<<<dim3(HH, BB * GG), 128>>>(x, dw);
    conv3_kernel<<<dim3(8, 8, BB * 8), 256>>>(roi, w1);
    conv1x1_kernel<<<dim3(256, 2, BB), 256>>>(out);
}